// round 14
// baseline (speedup 1.0000x reference)
#include <cuda_runtime.h>

// NSLayer: out = X + (w0 A + ... + w6 A^7 + w7 I) X,  A = I - X X^T.
// IDENTITY (R12): A^k X = X K^k with K = I - X^T X  =>  out = X * R,
//   R = E + K*O,  L = K^2,
//   E = (1+w7) I + w1 L + w3 L^2 + w5 L^3,   O = w0 I + w2 L + w4 L^2 + w6 L^3.
// All products are symmetric 8x8 -> triangle-only packed dots (fma.rn.f32x2).
// 262144 matrices, ONE thread per matrix. fma-pipe work ~3.5K cyc/warp.

static constexpr int MPB = 128;   // matrices per block == threads per block
static constexpr int MS  = 68;    // padded matrix stride in floats

typedef unsigned long long u64;

__device__ __forceinline__ u64 pack2(float lo, float hi) {
    u64 r; asm("mov.b64 %0, {%1, %2};" : "=l"(r) : "f"(lo), "f"(hi)); return r;
}
__device__ __forceinline__ void unpack2(u64 v, float& lo, float& hi) {
    asm("mov.b64 {%0, %1}, %2;" : "=f"(lo), "=f"(hi) : "l"(v));
}
__device__ __forceinline__ float hadd2(u64 v) {
    float lo, hi; asm("mov.b64 {%0, %1}, %2;" : "=f"(lo), "=f"(hi) : "l"(v));
    return lo + hi;
}
__device__ __forceinline__ u64 fma2(u64 a, u64 b, u64 c) {
    u64 d; asm("fma.rn.f32x2 %0, %1, %2, %3;" : "=l"(d) : "l"(a), "l"(b), "l"(c)); return d;
}
__device__ __forceinline__ u64 mul2(u64 a, u64 b) {
    u64 d; asm("mul.rn.f32x2 %0, %1, %2;" : "=l"(d) : "l"(a), "l"(b)); return d;
}

#define TRI(r, k) ((r) >= (k) ? ((r) * ((r) + 1) / 2 + (k)) : ((k) * ((k) + 1) / 2 + (r)))

// packed dot of two 8-float rows held as 4 pairs
__device__ __forceinline__ float dot8(const u64* a, const u64* b) {
    u64 d2 = mul2(a[0], b[0]);
    d2 = fma2(a[1], b[1], d2);
    d2 = fma2(a[2], b[2], d2);
    d2 = fma2(a[3], b[3], d2);
    return hadd2(d2);
}

__global__ __launch_bounds__(128, 2)
void nslayer_kernel(const float* __restrict__ x,
                    const float* __restrict__ weight,
                    float* __restrict__ out)
{
    __shared__ float s[MPB * MS];
    const int tid = threadIdx.x;
    const size_t base = (size_t)blockIdx.x * (MPB * 64);

    // ---- weights (scalar) ----
    const float4 wA4 = __ldg(reinterpret_cast<const float4*>(weight));
    const float4 wB4 = __ldg(reinterpret_cast<const float4*>(weight) + 1);
    const float w0 = wA4.x, w1 = wA4.y, w2 = wA4.z, w3 = wA4.w;
    const float w4 = wB4.x, w5 = wB4.y, w6 = wB4.z, w7p1 = wB4.w + 1.0f;

    // ---- coalesced load: block's 32KB chunk -> padded smem ----
    const float4* gin = reinterpret_cast<const float4*>(x + base);
#pragma unroll
    for (int k = 0; k < 16; k++) {
        int l4 = tid + k * 128;
        float4 v = gin[l4];
        int l = l4 << 2, m = l >> 6, w = l & 63;
        *reinterpret_cast<float4*>(&s[m * MS + w]) = v;
    }
    __syncthreads();

    // ---- load X rows, transpose in registers to column-pair form ----
    u64 Xt2[8][4];   // Xt2[c][rp] = {X[2rp][c], X[2rp+1][c]}
    {
        float xf[8][8];
#pragma unroll
        for (int r = 0; r < 8; r++) {
            ulonglong2 p0 = *reinterpret_cast<const ulonglong2*>(&s[tid * MS + r * 8]);
            ulonglong2 p1 = *reinterpret_cast<const ulonglong2*>(&s[tid * MS + r * 8 + 4]);
            unpack2(p0.x, xf[r][0], xf[r][1]);
            unpack2(p0.y, xf[r][2], xf[r][3]);
            unpack2(p1.x, xf[r][4], xf[r][5]);
            unpack2(p1.y, xf[r][6], xf[r][7]);
        }
#pragma unroll
        for (int c = 0; c < 8; c++)
#pragma unroll
            for (int rp = 0; rp < 4; rp++)
                Xt2[c][rp] = pack2(xf[2 * rp][c], xf[2 * rp + 1][c]);
    }

    // ---- K = I - X^T X (triangle scalars -> row-pair form) ----
    u64 Kp[8][4];
    {
        float Ks[36];
#pragma unroll
        for (int r = 0; r < 8; r++)
#pragma unroll
            for (int c = 0; c <= r; c++)
                Ks[TRI(r, c)] = ((r == c) ? 1.0f : 0.0f) - dot8(Xt2[r], Xt2[c]);
#pragma unroll
        for (int r = 0; r < 8; r++)
#pragma unroll
            for (int kp = 0; kp < 4; kp++)
                Kp[r][kp] = pack2(Ks[TRI(r, 2 * kp)], Ks[TRI(r, 2 * kp + 1)]);
    }   // Xt2 dies

    // ---- L = K^2 ; init E = w1 L, O = w2 L ----
    float E[36], O[36];
    u64 Lp[8][4];
    {
        float Ls[36];
#pragma unroll
        for (int r = 0; r < 8; r++)
#pragma unroll
            for (int c = 0; c <= r; c++) {
                float v = dot8(Kp[r], Kp[c]);
                int e = TRI(r, c);
                Ls[e] = v;
                E[e] = w1 * v;
                O[e] = w2 * v;
            }
#pragma unroll
        for (int r = 0; r < 8; r++)
#pragma unroll
            for (int kp = 0; kp < 4; kp++)
                Lp[r][kp] = pack2(Ls[TRI(r, 2 * kp)], Ls[TRI(r, 2 * kp + 1)]);
    }

    // ---- M = L^2 : fold E += w3 M, O += w4 M ; keep M as row pairs ----
    u64 Mp[8][4];
    {
        float Msc[36];
#pragma unroll
        for (int r = 0; r < 8; r++)
#pragma unroll
            for (int c = 0; c <= r; c++) {
                float v = dot8(Lp[r], Lp[c]);
                int e = TRI(r, c);
                Msc[e] = v;
                E[e] = fmaf(w3, v, E[e]);
                O[e] = fmaf(w4, v, O[e]);
            }
#pragma unroll
        for (int r = 0; r < 8; r++)
#pragma unroll
            for (int kp = 0; kp < 4; kp++)
                Mp[r][kp] = pack2(Msc[TRI(r, 2 * kp)], Msc[TRI(r, 2 * kp + 1)]);
    }

    // ---- L^3 = M*L : fold E += w5, O += w6 (never stored) ----
#pragma unroll
    for (int r = 0; r < 8; r++)
#pragma unroll
        for (int c = 0; c <= r; c++) {
            float v = dot8(Mp[r], Lp[c]);
            int e = TRI(r, c);
            E[e] = fmaf(w5, v, E[e]);
            O[e] = fmaf(w6, v, O[e]);
        }
    // Mp, Lp die

    // ---- diagonals: E += (1+w7) I, O += w0 I ----
#pragma unroll
    for (int r = 0; r < 8; r++) {
        E[TRI(r, r)] += w7p1;
        O[TRI(r, r)] += w0;
    }

    // ---- R = E + K*O  (row-pair form for the final product) ----
    u64 Rp[8][4];
    {
        u64 Op[8][4];
#pragma unroll
        for (int r = 0; r < 8; r++)
#pragma unroll
            for (int kp = 0; kp < 4; kp++)
                Op[r][kp] = pack2(O[TRI(r, 2 * kp)], O[TRI(r, 2 * kp + 1)]);
        float Rs[36];
#pragma unroll
        for (int r = 0; r < 8; r++)
#pragma unroll
            for (int c = 0; c <= r; c++) {
                int e = TRI(r, c);
                Rs[e] = E[e] + dot8(Kp[r], Op[c]);
            }
#pragma unroll
        for (int r = 0; r < 8; r++)
#pragma unroll
            for (int kp = 0; kp < 4; kp++)
                Rp[r][kp] = pack2(Rs[TRI(r, 2 * kp)], Rs[TRI(r, 2 * kp + 1)]);
    }   // E, O, Kp die

    // ---- out = X * R : per row, X scalars broadcast x R row-pairs ----
#pragma unroll
    for (int r = 0; r < 8; r++) {
        ulonglong2 p0 = *reinterpret_cast<const ulonglong2*>(&s[tid * MS + r * 8]);
        ulonglong2 p1 = *reinterpret_cast<const ulonglong2*>(&s[tid * MS + r * 8 + 4]);
        float xr[8];
        unpack2(p0.x, xr[0], xr[1]);
        unpack2(p0.y, xr[2], xr[3]);
        unpack2(p1.x, xr[4], xr[5]);
        unpack2(p1.y, xr[6], xr[7]);
        u64 xb[8];
#pragma unroll
        for (int k = 0; k < 8; k++) xb[k] = pack2(xr[k], xr[k]);
        u64 acc[4];
#pragma unroll
        for (int cp = 0; cp < 4; cp++) acc[cp] = mul2(xb[0], Rp[0][cp]);
#pragma unroll
        for (int k = 1; k < 8; k++)
#pragma unroll
            for (int cp = 0; cp < 4; cp++)
                acc[cp] = fma2(xb[k], Rp[k][cp], acc[cp]);
        ulonglong2 q0, q1;
        q0.x = acc[0]; q0.y = acc[1]; q1.x = acc[2]; q1.y = acc[3];
        *reinterpret_cast<ulonglong2*>(&s[tid * MS + r * 8])     = q0;
        *reinterpret_cast<ulonglong2*>(&s[tid * MS + r * 8 + 4]) = q1;
    }
    __syncthreads();

    // ---- coalesced store: padded smem -> block's 32KB output chunk ----
    float4* gout = reinterpret_cast<float4*>(out + base);
#pragma unroll
    for (int k = 0; k < 16; k++) {
        int l4 = tid + k * 128;
        int l = l4 << 2, m = l >> 6, w = l & 63;
        gout[l4] = *reinterpret_cast<const float4*>(&s[m * MS + w]);
    }
}

extern "C" void kernel_launch(void* const* d_in, const int* in_sizes, int n_in,
                              void* d_out, int out_size) {
    const float* x = (const float*)d_in[0];
    const float* w = (const float*)d_in[1];
    float* out = (float*)d_out;
    int nmat = in_sizes[0] / 64;          // 262144
    int blocks = nmat / MPB;              // 2048 (exact)
    nslayer_kernel<<<blocks, MPB>>>(x, w, out);
}

// round 15
// speedup vs baseline: 1.2605x; 1.2605x over previous
#include <cuda_runtime.h>

// NSLayer: out = X + (w0 A + ... + w6 A^7 + w7 I) X,  A = I - X X^T
// 262144 independent 8x8 fp32 matrices, ONE thread per matrix.
// R13 = R7 skeleton (B=A^2 even/odd split: V=BX,W=BV,Z=BW;
//   t = w0X+w2V+w4W+w6Z; u=(1+w7)X+w1V+w3W+w5Z; out = u + A t;
//   broadcast-form operands ONLY inside the chains -> alu-free hot path)
// with ONE change: B built via packed dots over A's rows (A symmetric),
// 288 -> 144 fma2; the 36 hadds are mutually independent and pre-chain.
// fma2/thread = 1568 @ FFMA2 rt=3 (RF-bank floor).

static constexpr int MPB = 128;   // matrices per block == threads per block
static constexpr int MS  = 68;    // padded matrix stride in floats

typedef unsigned long long u64;

__device__ __forceinline__ u64 pack2(float lo, float hi) {
    u64 r; asm("mov.b64 %0, {%1, %2};" : "=l"(r) : "f"(lo), "f"(hi)); return r;
}
__device__ __forceinline__ float hadd2(u64 v) {
    float lo, hi; asm("mov.b64 {%0, %1}, %2;" : "=f"(lo), "=f"(hi) : "l"(v));
    return lo + hi;
}
__device__ __forceinline__ u64 fma2(u64 a, u64 b, u64 c) {
    u64 d; asm("fma.rn.f32x2 %0, %1, %2, %3;" : "=l"(d) : "l"(a), "l"(b), "l"(c)); return d;
}
__device__ __forceinline__ u64 mul2(u64 a, u64 b) {
    u64 d; asm("mul.rn.f32x2 %0, %1, %2;" : "=l"(d) : "l"(a), "l"(b)); return d;
}

#define TRI(r, k) ((r) >= (k) ? ((r) * ((r) + 1) / 2 + (k)) : ((k) * ((k) + 1) / 2 + (r)))

__global__ __launch_bounds__(128, 2)
void nslayer_kernel(const float* __restrict__ x,
                    const float* __restrict__ weight,
                    float* __restrict__ out)
{
    __shared__ float s[MPB * MS];
    const int tid = threadIdx.x;
    const size_t base = (size_t)blockIdx.x * (MPB * 64);

    // ---- preload weights, pre-broadcast ----
    const float4 wA4 = __ldg(reinterpret_cast<const float4*>(weight));
    const float4 wB4 = __ldg(reinterpret_cast<const float4*>(weight) + 1);
    const u64 w0_2 = pack2(wA4.x, wA4.x);
    const u64 w1_2 = pack2(wA4.y, wA4.y);
    const u64 w2_2 = pack2(wA4.z, wA4.z);
    const u64 w3_2 = pack2(wA4.w, wA4.w);
    const u64 w4_2 = pack2(wB4.x, wB4.x);
    const u64 w5_2 = pack2(wB4.y, wB4.y);
    const u64 w6_2 = pack2(wB4.z, wB4.z);
    const float w7p1 = wB4.w + 1.0f;
    const u64 w7p1_2 = pack2(w7p1, w7p1);

    // ---- coalesced load: block's 32KB chunk -> padded smem ----
    const float4* gin = reinterpret_cast<const float4*>(x + base);
#pragma unroll
    for (int k = 0; k < 16; k++) {
        int l4 = tid + k * 128;
        float4 v = gin[l4];
        int l = l4 << 2, m = l >> 6, w = l & 63;
        *reinterpret_cast<float4*>(&s[m * MS + w]) = v;
    }
    __syncthreads();

    // ---- Gram: A = I - X X^T, scalar triangle Cs (packed row dots) ----
    float Cs[36];
    {
        u64 X2[8][4];
#pragma unroll
        for (int r = 0; r < 8; r++) {
            ulonglong2 p0 = *reinterpret_cast<const ulonglong2*>(&s[tid * MS + r * 8]);
            ulonglong2 p1 = *reinterpret_cast<const ulonglong2*>(&s[tid * MS + r * 8 + 4]);
            X2[r][0] = p0.x; X2[r][1] = p0.y; X2[r][2] = p1.x; X2[r][3] = p1.y;
        }
#pragma unroll
        for (int r = 0; r < 8; r++)
#pragma unroll
            for (int c = 0; c <= r; c++) {
                u64 d2 = mul2(X2[r][0], X2[c][0]);
#pragma unroll
                for (int kp = 1; kp < 4; kp++) d2 = fma2(X2[r][kp], X2[c][kp], d2);
                Cs[TRI(r, c)] = ((r == c) ? 1.0f : 0.0f) - hadd2(d2);
            }
    }   // X2 dies

    // ---- B = A*A via packed dots over A's rows (A symmetric):
    //      36 independent dots, alu (hadds/packs) overlaps with fma ----
    u64 B2b[36];
    {
        u64 A2p[8][4];
#pragma unroll
        for (int r = 0; r < 8; r++)
#pragma unroll
            for (int kp = 0; kp < 4; kp++)
                A2p[r][kp] = pack2(Cs[TRI(r, 2 * kp)], Cs[TRI(r, 2 * kp + 1)]);
#pragma unroll
        for (int r = 0; r < 8; r++)
#pragma unroll
            for (int c = 0; c <= r; c++) {
                u64 d2 = mul2(A2p[r][0], A2p[c][0]);
#pragma unroll
                for (int kp = 1; kp < 4; kp++) d2 = fma2(A2p[r][kp], A2p[c][kp], d2);
                float v = hadd2(d2);
                B2b[TRI(r, c)] = pack2(v, v);
            }
    }   // A2p dies

    // ---- A broadcast form for the final matvec ----
    u64 A2b[36];
#pragma unroll
    for (int e = 0; e < 36; e++) A2b[e] = pack2(Cs[e], Cs[e]);
    // Cs dies

    // ---- per column-pair: V=BX, W=BV, Z=BW; t,u folds; o = u + A t ----
#pragma unroll
    for (int cp = 0; cp < 4; cp++) {
        u64 xv[8], t[8], u[8], v[8];
#pragma unroll
        for (int k = 0; k < 8; k++)
            xv[k] = *reinterpret_cast<const u64*>(&s[tid * MS + k * 8 + 2 * cp]);
        // v = B x
#pragma unroll
        for (int r = 0; r < 8; r++) {
            u64 d2 = mul2(B2b[TRI(r, 0)], xv[0]);
#pragma unroll
            for (int k = 1; k < 8; k++) d2 = fma2(B2b[TRI(r, k)], xv[k], d2);
            v[r] = d2;
        }
#pragma unroll
        for (int r = 0; r < 8; r++) {
            t[r] = fma2(w2_2, v[r], mul2(w0_2, xv[r]));
            u[r] = fma2(w1_2, v[r], mul2(w7p1_2, xv[r]));
        }
        // w = B v (into xv)
#pragma unroll
        for (int r = 0; r < 8; r++) {
            u64 d2 = mul2(B2b[TRI(r, 0)], v[0]);
#pragma unroll
            for (int k = 1; k < 8; k++) d2 = fma2(B2b[TRI(r, k)], v[k], d2);
            xv[r] = d2;
        }
#pragma unroll
        for (int r = 0; r < 8; r++) {
            t[r] = fma2(w4_2, xv[r], t[r]);
            u[r] = fma2(w3_2, xv[r], u[r]);
        }
        // z = B w (into v)
#pragma unroll
        for (int r = 0; r < 8; r++) {
            u64 d2 = mul2(B2b[TRI(r, 0)], xv[0]);
#pragma unroll
            for (int k = 1; k < 8; k++) d2 = fma2(B2b[TRI(r, k)], xv[k], d2);
            v[r] = d2;
        }
#pragma unroll
        for (int r = 0; r < 8; r++) {
            t[r] = fma2(w6_2, v[r], t[r]);
            u[r] = fma2(w5_2, v[r], u[r]);
        }
        // o = u + A t, store this column pair
#pragma unroll
        for (int r = 0; r < 8; r++) {
            u64 d2 = u[r];
#pragma unroll
            for (int k = 0; k < 8; k++) d2 = fma2(A2b[TRI(r, k)], t[k], d2);
            *reinterpret_cast<u64*>(&s[tid * MS + r * 8 + 2 * cp]) = d2;
        }
    }
    __syncthreads();

    // ---- coalesced store: padded smem -> block's 32KB output chunk ----
    float4* gout = reinterpret_cast<float4*>(out + base);
#pragma unroll
    for (int k = 0; k < 16; k++) {
        int l4 = tid + k * 128;
        int l = l4 << 2, m = l >> 6, w = l & 63;
        gout[l4] = *reinterpret_cast<const float4*>(&s[m * MS + w]);
    }
}

extern "C" void kernel_launch(void* const* d_in, const int* in_sizes, int n_in,
                              void* d_out, int out_size) {
    const float* x = (const float*)d_in[0];
    const float* w = (const float*)d_in[1];
    float* out = (float*)d_out;
    int nmat = in_sizes[0] / 64;          // 262144
    int blocks = nmat / MPB;              // 2048 (exact)
    nslayer_kernel<<<blocks, MPB>>>(x, w, out);
}

// round 16
// speedup vs baseline: 1.3059x; 1.0360x over previous
#include <cuda_runtime.h>

// NSLayer: out = X + (w0 A + ... + w6 A^7 + w7 I) X,  A = I - X X^T
// 262144 independent 8x8 fp32 matrices, ONE thread per matrix.
// R14 = R13 algebra (B=A^2 even/odd split, packed-dot B build, broadcast-only
// chains) + "#pragma unroll 1" on the cp-chain loop so only ONE chain's
// transients (xv,t,u,v = 64 regs) are ever live -> no spills at 2 CTAs/SM.
// fma2/thread ~1568 @ FFMA2 rt=3 (RF-bank floor ~32us kernel).

static constexpr int MPB = 128;   // matrices per block == threads per block
static constexpr int MS  = 68;    // padded matrix stride in floats

typedef unsigned long long u64;

__device__ __forceinline__ u64 pack2(float lo, float hi) {
    u64 r; asm("mov.b64 %0, {%1, %2};" : "=l"(r) : "f"(lo), "f"(hi)); return r;
}
__device__ __forceinline__ float hadd2(u64 v) {
    float lo, hi; asm("mov.b64 {%0, %1}, %2;" : "=f"(lo), "=f"(hi) : "l"(v));
    return lo + hi;
}
__device__ __forceinline__ u64 fma2(u64 a, u64 b, u64 c) {
    u64 d; asm("fma.rn.f32x2 %0, %1, %2, %3;" : "=l"(d) : "l"(a), "l"(b), "l"(c)); return d;
}
__device__ __forceinline__ u64 mul2(u64 a, u64 b) {
    u64 d; asm("mul.rn.f32x2 %0, %1, %2;" : "=l"(d) : "l"(a), "l"(b)); return d;
}

#define TRI(r, k) ((r) >= (k) ? ((r) * ((r) + 1) / 2 + (k)) : ((k) * ((k) + 1) / 2 + (r)))

__global__ __launch_bounds__(128, 2)
void nslayer_kernel(const float* __restrict__ x,
                    const float* __restrict__ weight,
                    float* __restrict__ out)
{
    __shared__ float s[MPB * MS];
    const int tid = threadIdx.x;
    const size_t base = (size_t)blockIdx.x * (MPB * 64);

    // ---- preload weights, pre-broadcast ----
    const float4 wA4 = __ldg(reinterpret_cast<const float4*>(weight));
    const float4 wB4 = __ldg(reinterpret_cast<const float4*>(weight) + 1);
    const u64 w0_2 = pack2(wA4.x, wA4.x);
    const u64 w1_2 = pack2(wA4.y, wA4.y);
    const u64 w2_2 = pack2(wA4.z, wA4.z);
    const u64 w3_2 = pack2(wA4.w, wA4.w);
    const u64 w4_2 = pack2(wB4.x, wB4.x);
    const u64 w5_2 = pack2(wB4.y, wB4.y);
    const u64 w6_2 = pack2(wB4.z, wB4.z);
    const float w7p1 = wB4.w + 1.0f;
    const u64 w7p1_2 = pack2(w7p1, w7p1);

    // ---- coalesced load: block's 32KB chunk -> padded smem ----
    const float4* gin = reinterpret_cast<const float4*>(x + base);
#pragma unroll
    for (int k = 0; k < 16; k++) {
        int l4 = tid + k * 128;
        float4 v = gin[l4];
        int l = l4 << 2, m = l >> 6, w = l & 63;
        *reinterpret_cast<float4*>(&s[m * MS + w]) = v;
    }
    __syncthreads();

    // ---- Gram: A = I - X X^T; pack straight into row-pair (A2p) and
    //      broadcast (A2b) forms, no scalar array kept ----
    u64 A2p[8][4];
    u64 A2b[36];
    {
        u64 X2[8][4];
#pragma unroll
        for (int r = 0; r < 8; r++) {
            ulonglong2 p0 = *reinterpret_cast<const ulonglong2*>(&s[tid * MS + r * 8]);
            ulonglong2 p1 = *reinterpret_cast<const ulonglong2*>(&s[tid * MS + r * 8 + 4]);
            X2[r][0] = p0.x; X2[r][1] = p0.y; X2[r][2] = p1.x; X2[r][3] = p1.y;
        }
        float Cs[36];
#pragma unroll
        for (int r = 0; r < 8; r++)
#pragma unroll
            for (int c = 0; c <= r; c++) {
                u64 d2 = mul2(X2[r][0], X2[c][0]);
#pragma unroll
                for (int kp = 1; kp < 4; kp++) d2 = fma2(X2[r][kp], X2[c][kp], d2);
                float v = ((r == c) ? 1.0f : 0.0f) - hadd2(d2);
                Cs[TRI(r, c)] = v;
                A2b[TRI(r, c)] = pack2(v, v);
            }
#pragma unroll
        for (int r = 0; r < 8; r++)
#pragma unroll
            for (int kp = 0; kp < 4; kp++)
                A2p[r][kp] = pack2(Cs[TRI(r, 2 * kp)], Cs[TRI(r, 2 * kp + 1)]);
    }   // X2, Cs die

    // ---- B = A*A via packed dots over A's rows (A symmetric):
    //      36 independent dots; hadds/packs overlap with fma ----
    u64 B2b[36];
#pragma unroll
    for (int r = 0; r < 8; r++)
#pragma unroll
        for (int c = 0; c <= r; c++) {
            u64 d2 = mul2(A2p[r][0], A2p[c][0]);
#pragma unroll
            for (int kp = 1; kp < 4; kp++) d2 = fma2(A2p[r][kp], A2p[c][kp], d2);
            float v = hadd2(d2);
            B2b[TRI(r, c)] = pack2(v, v);
        }
    // A2p dies. Persistent through chains: B2b(72) + A2b(72) + weights(16).

    // ---- per column-pair: V=BX, W=BV, Z=BW; t,u folds; o = u + A t.
    //      unroll 1: only ONE chain's transients live at a time ----
#pragma unroll 1
    for (int cp = 0; cp < 4; cp++) {
        u64 xv[8], t[8], u[8], v[8];
#pragma unroll
        for (int k = 0; k < 8; k++)
            xv[k] = *reinterpret_cast<const u64*>(&s[tid * MS + k * 8 + 2 * cp]);
        // v = B x
#pragma unroll
        for (int r = 0; r < 8; r++) {
            u64 d2 = mul2(B2b[TRI(r, 0)], xv[0]);
#pragma unroll
            for (int k = 1; k < 8; k++) d2 = fma2(B2b[TRI(r, k)], xv[k], d2);
            v[r] = d2;
        }
#pragma unroll
        for (int r = 0; r < 8; r++) {
            t[r] = fma2(w2_2, v[r], mul2(w0_2, xv[r]));
            u[r] = fma2(w1_2, v[r], mul2(w7p1_2, xv[r]));
        }
        // w = B v (into xv)
#pragma unroll
        for (int r = 0; r < 8; r++) {
            u64 d2 = mul2(B2b[TRI(r, 0)], v[0]);
#pragma unroll
            for (int k = 1; k < 8; k++) d2 = fma2(B2b[TRI(r, k)], v[k], d2);
            xv[r] = d2;
        }
#pragma unroll
        for (int r = 0; r < 8; r++) {
            t[r] = fma2(w4_2, xv[r], t[r]);
            u[r] = fma2(w3_2, xv[r], u[r]);
        }
        // z = B w (into v)
#pragma unroll
        for (int r = 0; r < 8; r++) {
            u64 d2 = mul2(B2b[TRI(r, 0)], xv[0]);
#pragma unroll
            for (int k = 1; k < 8; k++) d2 = fma2(B2b[TRI(r, k)], xv[k], d2);
            v[r] = d2;
        }
#pragma unroll
        for (int r = 0; r < 8; r++) {
            t[r] = fma2(w6_2, v[r], t[r]);
            u[r] = fma2(w5_2, v[r], u[r]);
        }
        // o = u + A t, store this column pair
#pragma unroll
        for (int r = 0; r < 8; r++) {
            u64 d2 = u[r];
#pragma unroll
            for (int k = 0; k < 8; k++) d2 = fma2(A2b[TRI(r, k)], t[k], d2);
            *reinterpret_cast<u64*>(&s[tid * MS + r * 8 + 2 * cp]) = d2;
        }
    }
    __syncthreads();

    // ---- coalesced store: padded smem -> block's 32KB output chunk ----
    float4* gout = reinterpret_cast<float4*>(out + base);
#pragma unroll
    for (int k = 0; k < 16; k++) {
        int l4 = tid + k * 128;
        int l = l4 << 2, m = l >> 6, w = l & 63;
        gout[l4] = *reinterpret_cast<const float4*>(&s[m * MS + w]);
    }
}

extern "C" void kernel_launch(void* const* d_in, const int* in_sizes, int n_in,
                              void* d_out, int out_size) {
    const float* x = (const float*)d_in[0];
    const float* w = (const float*)d_in[1];
    float* out = (float*)d_out;
    int nmat = in_sizes[0] / 64;          // 262144
    int blocks = nmat / MPB;              // 2048 (exact)
    nslayer_kernel<<<blocks, MPB>>>(x, w, out);
}